// round 1
// baseline (speedup 1.0000x reference)
#include <cuda_runtime.h>
#include <cuda_bf16.h>

// Problem constants
#define B_  16
#define T_  512
#define H_  2048
#define W_STRIDE 4096   // W is [H, 2H] row-major

// 64 MB scratch for u = x @ Wx^T + b   (B*T, H)
__device__ float g_u[B_ * T_ * H_];

// ---------------------------------------------------------------------------
// Phase 1: u[m, n] = sum_k X[m,k] * W[n, k] + bias[n]   (m = b*T+t, n = g)
// 64x64 tile, TK=16, 256 threads, 4x4 per thread, fp32.
// ---------------------------------------------------------------------------
#define TM 64
#define TN 64
#define TK 16

__global__ __launch_bounds__(256) void u_gemm_kernel(
    const float* __restrict__ X, const float* __restrict__ W,
    const float* __restrict__ bias, float* __restrict__ U)
{
    __shared__ __align__(16) float As[TK][TM + 4];  // +4 pad keeps 16B align, reduces STS conflicts
    __shared__ __align__(16) float Bs[TK][TN + 4];

    const int n0 = blockIdx.x * TN;
    const int m0 = blockIdx.y * TM;
    const int tid = threadIdx.x;
    const int tx = tid & 15;         // -> m micro-tile
    const int ty = tid >> 4;         // -> n micro-tile

    float acc[4][4];
#pragma unroll
    for (int i = 0; i < 4; i++)
#pragma unroll
        for (int j = 0; j < 4; j++) acc[i][j] = 0.f;

    const int lk = tid & 15;         // k within tile
    const int lm = tid >> 4;         // row group (16 rows per pass)

    for (int k0 = 0; k0 < H_; k0 += TK) {
#pragma unroll
        for (int p = 0; p < 4; p++) {
            int m = lm + p * 16;
            As[lk][m] = X[(m0 + m) * H_ + k0 + lk];
            Bs[lk][m] = W[(size_t)(n0 + m) * W_STRIDE + k0 + lk];
        }
        __syncthreads();
#pragma unroll
        for (int kk = 0; kk < TK; kk++) {
            float4 a = *(const float4*)&As[kk][tx * 4];
            float4 b = *(const float4*)&Bs[kk][ty * 4];
            acc[0][0] += a.x * b.x; acc[0][1] += a.x * b.y; acc[0][2] += a.x * b.z; acc[0][3] += a.x * b.w;
            acc[1][0] += a.y * b.x; acc[1][1] += a.y * b.y; acc[1][2] += a.y * b.z; acc[1][3] += a.y * b.w;
            acc[2][0] += a.z * b.x; acc[2][1] += a.z * b.y; acc[2][2] += a.z * b.z; acc[2][3] += a.z * b.w;
            acc[3][0] += a.w * b.x; acc[3][1] += a.w * b.y; acc[3][2] += a.w * b.z; acc[3][3] += a.w * b.w;
        }
        __syncthreads();
    }

#pragma unroll
    for (int i = 0; i < 4; i++) {
        int m = m0 + tx * 4 + i;
#pragma unroll
        for (int j = 0; j < 4; j++) {
            int n = n0 + ty * 4 + j;
            U[m * H_ + n] = acc[i][j] + bias[n];
        }
    }
}

// ---------------------------------------------------------------------------
// Phase 2, step t (t >= 1):
//   out[b, t, g] = u[b, t, g] + sum_k out[b, t-1, k] * W[g, H + k]
// Grid: 128 blocks * 256 threads. Block handles 16 g's (warp -> 2 g).
// h_prev (16x2048 fp32 = 128 KB) staged in dynamic SMEM, float4 everywhere.
// ---------------------------------------------------------------------------
__global__ __launch_bounds__(256) void step_kernel(
    const float* __restrict__ W, const float* __restrict__ U,
    float* __restrict__ out, int t)
{
    extern __shared__ __align__(16) float hs[];  // [16][2048]
    const int tid = threadIdx.x;

    // load h_prev = out[:, t-1, :]
    for (int i = tid; i < (B_ * H_) / 4; i += 256) {
        int e = i * 4;
        int b = e >> 11;            // /2048
        int k = e & (H_ - 1);
        float4 v = *(const float4*)&out[((b * T_ + (t - 1)) * H_) + k];
        *(float4*)&hs[b * H_ + k] = v;
    }
    __syncthreads();

    const int warp = tid >> 5;
    const int lane = tid & 31;
    const int g0 = blockIdx.x * 16 + warp * 2;

    const float* w0 = &W[(size_t)g0 * W_STRIDE + H_];
    const float* w1 = w0 + W_STRIDE;

    float acc0[16], acc1[16];
#pragma unroll
    for (int b = 0; b < 16; b++) { acc0[b] = 0.f; acc1[b] = 0.f; }

    for (int k0 = lane * 4; k0 < H_; k0 += 128) {
        float4 wa = *(const float4*)&w0[k0];
        float4 wb = *(const float4*)&w1[k0];
#pragma unroll
        for (int b = 0; b < 16; b++) {
            float4 h = *(const float4*)&hs[b * H_ + k0];
            acc0[b] += h.x * wa.x + h.y * wa.y + h.z * wa.z + h.w * wa.w;
            acc1[b] += h.x * wb.x + h.y * wb.y + h.z * wb.z + h.w * wb.w;
        }
    }

#pragma unroll
    for (int b = 0; b < 16; b++) {
        float v0 = acc0[b];
        float v1 = acc1[b];
#pragma unroll
        for (int off = 16; off > 0; off >>= 1) {
            v0 += __shfl_xor_sync(0xffffffffu, v0, off);
            v1 += __shfl_xor_sync(0xffffffffu, v1, off);
        }
        if (lane == 0) {
            int o = (b * T_ + t) * H_;
            out[o + g0]     = v0 + U[o + g0];
            out[o + g0 + 1] = v1 + U[o + g0 + 1];
        }
    }
}

// Step 0: out[:, 0, :] = u[:, 0, :]
__global__ __launch_bounds__(256) void step0_kernel(
    const float* __restrict__ U, float* __restrict__ out)
{
    int i = blockIdx.x * blockDim.x + threadIdx.x;   // over B*H
    if (i < B_ * H_) {
        int b = i >> 11;
        int g = i & (H_ - 1);
        int o = (b * T_) * H_ + g;   // t = 0
        out[o] = U[o];
    }
}

// Tail: h_last = out[:, T-1, :]
__global__ __launch_bounds__(256) void tail_kernel(float* __restrict__ out)
{
    int i = blockIdx.x * blockDim.x + threadIdx.x;   // over B*H
    if (i < B_ * H_) {
        int b = i >> 11;
        int g = i & (H_ - 1);
        out[(size_t)B_ * T_ * H_ + i] = out[(b * T_ + (T_ - 1)) * H_ + g];
    }
}

extern "C" void kernel_launch(void* const* d_in, const int* in_sizes, int n_in,
                              void* d_out, int out_size)
{
    const float* x    = (const float*)d_in[0];   // [16, 512, 2048]
    const float* W    = (const float*)d_in[1];   // [2048, 4096]
    const float* bias = (const float*)d_in[2];   // [2048]
    float* out = (float*)d_out;                  // [16*512*2048 + 16*2048]

    float* U = nullptr;
    cudaGetSymbolAddress((void**)&U, g_u);

    // opt-in to 128 KB dynamic smem for the step kernel (idempotent, capture-safe)
    static_assert(B_ * H_ * sizeof(float) == 131072, "smem size");
    cudaFuncSetAttribute(step_kernel, cudaFuncAttributeMaxDynamicSharedMemorySize, 131072);

    // Phase 1: u
    dim3 ggrid(H_ / TN, (B_ * T_) / TM);
    u_gemm_kernel<<<ggrid, 256>>>(x, W, bias, U);

    // Phase 2: recurrence (out buffer doubles as h history)
    step0_kernel<<<(B_ * H_ + 255) / 256, 256>>>(U, out);
    for (int t = 1; t < T_; t++) {
        step_kernel<<<128, 256, 131072>>>(W, U, out, t);
    }

    // h_last
    tail_kernel<<<(B_ * H_ + 255) / 256, 256>>>(out);
}

// round 3
// speedup vs baseline: 1.4370x; 1.4370x over previous
#include <cuda_runtime.h>
#include <cuda_bf16.h>

// Problem constants
#define B_  16
#define T_  512
#define H_  2048
#define W_STRIDE 4096   // W is [H, 2H] row-major
#define NCTA 128
#define NTHR 256

// 64 MB scratch for u = x @ Wx^T + b   (B*T, H)
__device__ float g_u[B_ * T_ * H_];
// grid barrier counter (monotonic within one launch; reset per replay)
__device__ volatile unsigned g_arrive;

__global__ void init_kernel() { g_arrive = 0u; }

// packed f32x2 FMA: d = a*b + c (elementwise on 2 packed floats)
__device__ __forceinline__ unsigned long long ffma2(
    unsigned long long a, unsigned long long b, unsigned long long c)
{
    unsigned long long d;
    asm("fma.rn.f32x2 %0, %1, %2, %3;" : "=l"(d) : "l"(a), "l"(b), "l"(c));
    return d;
}

// ---------------------------------------------------------------------------
// Phase 1: u[m, n] = sum_k X[m,k] * W[n, k] + bias[n]
// ---------------------------------------------------------------------------
#define TM 64
#define TN 64
#define TK 16

__global__ __launch_bounds__(256) void u_gemm_kernel(
    const float* __restrict__ X, const float* __restrict__ W,
    const float* __restrict__ bias, float* __restrict__ U)
{
    __shared__ __align__(16) float As[TK][TM + 4];
    __shared__ __align__(16) float Bs[TK][TN + 4];

    const int n0 = blockIdx.x * TN;
    const int m0 = blockIdx.y * TM;
    const int tid = threadIdx.x;
    const int tx = tid & 15;
    const int ty = tid >> 4;

    float acc[4][4];
#pragma unroll
    for (int i = 0; i < 4; i++)
#pragma unroll
        for (int j = 0; j < 4; j++) acc[i][j] = 0.f;

    const int lk = tid & 15;
    const int lm = tid >> 4;

    for (int k0 = 0; k0 < H_; k0 += TK) {
#pragma unroll
        for (int p = 0; p < 4; p++) {
            int m = lm + p * 16;
            As[lk][m] = X[(m0 + m) * H_ + k0 + lk];
            Bs[lk][m] = W[(size_t)(n0 + m) * W_STRIDE + k0 + lk];
        }
        __syncthreads();
#pragma unroll
        for (int kk = 0; kk < TK; kk++) {
            float4 a = *(const float4*)&As[kk][tx * 4];
            float4 b = *(const float4*)&Bs[kk][ty * 4];
            acc[0][0] += a.x * b.x; acc[0][1] += a.x * b.y; acc[0][2] += a.x * b.z; acc[0][3] += a.x * b.w;
            acc[1][0] += a.y * b.x; acc[1][1] += a.y * b.y; acc[1][2] += a.y * b.z; acc[1][3] += a.y * b.w;
            acc[2][0] += a.z * b.x; acc[2][1] += a.z * b.y; acc[2][2] += a.z * b.z; acc[2][3] += a.z * b.w;
            acc[3][0] += a.w * b.x; acc[3][1] += a.w * b.y; acc[3][2] += a.w * b.z; acc[3][3] += a.w * b.w;
        }
        __syncthreads();
    }

#pragma unroll
    for (int i = 0; i < 4; i++) {
        int m = m0 + tx * 4 + i;
#pragma unroll
        for (int j = 0; j < 4; j++) {
            int n = n0 + ty * 4 + j;
            U[m * H_ + n] = acc[i][j] + bias[n];
        }
    }
}

// ---------------------------------------------------------------------------
// Phase 2: persistent recurrence. 128 CTAs x 256 thr, 1 CTA/SM, spin barrier.
// CTA owns 16 g. Warp layout: gGroup(2 x 8g) x bGroup(2 x 8b) x kHalf(2 x 1024k).
// Lane covers k = kHalf*1024 + it*128 + lane*4, 8 iters, float4/f32x2 packed.
// SMEM: hs[16*2048] | us[256] (U slice) | red[256] (kHalf-1 partials)
// ---------------------------------------------------------------------------
#define SMEM_FLOATS (B_ * H_ + 256 + 256)

__global__ __launch_bounds__(NTHR, 1) void rnn_persistent_kernel(
    const float* __restrict__ W, const float* __restrict__ U,
    float* __restrict__ out)
{
    extern __shared__ __align__(16) float hs[];   // [16][2048]
    float* us  = hs + B_ * H_;                    // [16 b][16 gl]
    float* red = us + 256;                        // [16 gl][16 b]

    const int tid  = threadIdx.x;
    const int warp = tid >> 5;
    const int lane = tid & 31;
    const int gGroup = warp & 1;          // which 8 g's
    const int bGroup = (warp >> 1) & 1;   // which 8 b's
    const int kHalf  = warp >> 2;         // which 1024 k's
    const int gbase = blockIdx.x * 16;

    // per-g W row base pointers (Wh part), offset to this warp's k-half
    const float* wb[8];
#pragma unroll
    for (int g = 0; g < 8; g++)
        wb[g] = W + (size_t)(gbase + gGroup * 8 + g) * W_STRIDE + H_ + kHalf * 1024;

    // ---- t = 0: out[:, 0, slice] = U[:, 0, slice] ----
    {
        int b = tid >> 4;
        int gl = tid & 15;
        int o = (b * T_) * H_ + gbase + gl;
        out[o] = __ldcg(&U[o]);
    }
    __threadfence();
    __syncthreads();
    if (tid == 0) atomicAdd((unsigned*)&g_arrive, 1u);

    for (int t = 1; t < T_; t++) {
        // ---- grid barrier ----
        if (tid == 0) {
            unsigned target = (unsigned)(NCTA * t);
            while (g_arrive < target) __nanosleep(64);
            __threadfence();   // acquire
        }
        __syncthreads();

        // ---- stage h_{t-1} into smem via L2 (don't evict W from L1) ----
#pragma unroll 4
        for (int i = tid; i < (B_ * H_) / 4; i += NTHR) {
            int e = i * 4;
            int b = e >> 11;
            int k = e & (H_ - 1);
            float4 v = __ldcg((const float4*)&out[((size_t)(b * T_ + (t - 1))) * H_ + k]);
            *(float4*)&hs[b * H_ + k] = v;
        }
        {   // stage this step's U slice: us[b*16 + gl]
            int b = tid >> 4;
            int gl = tid & 15;
            us[tid] = __ldcg(&U[((size_t)(b * T_ + t)) * H_ + gbase + gl]);
        }
        __syncthreads();

        // ---- compute: acc[b][g] as packed f32x2 ----
        unsigned long long acc[8][8];
#pragma unroll
        for (int b = 0; b < 8; b++)
#pragma unroll
            for (int g = 0; g < 8; g++) acc[b][g] = 0ull;

#pragma unroll
        for (int it = 0; it < 8; it++) {
            const int k0 = it * 128 + lane * 4;
            ulonglong2 wv[8];
#pragma unroll
            for (int g = 0; g < 8; g++)
                wv[g] = __ldg((const ulonglong2*)&wb[g][k0]);
#pragma unroll
            for (int b = 0; b < 8; b++) {
                ulonglong2 hv = *(const ulonglong2*)&hs[(bGroup * 8 + b) * H_ + kHalf * 1024 + k0];
#pragma unroll
                for (int g = 0; g < 8; g++) {
                    acc[b][g] = ffma2(hv.x, wv[g].x, acc[b][g]);
                    acc[b][g] = ffma2(hv.y, wv[g].y, acc[b][g]);
                }
            }
        }

        // ---- reduce across lanes; keep pair p at lane (p & 31) ----
        float keep0 = 0.f, keep1 = 0.f;   // pairs p = lane, p = lane + 32
#pragma unroll
        for (int b = 0; b < 8; b++) {
#pragma unroll
            for (int g = 0; g < 8; g++) {
                float2 f2 = *(float2*)&acc[b][g];
                float p = f2.x + f2.y;
#pragma unroll
                for (int off = 16; off > 0; off >>= 1)
                    p += __shfl_xor_sync(0xffffffffu, p, off);
                int pidx = b * 8 + g;
                if (lane == (pidx & 31)) {
                    if (pidx < 32) keep0 = p; else keep1 = p;
                }
            }
        }

        // kHalf 1 publishes partials; kHalf 0 combines, adds U, stores.
        if (kHalf == 1) {
            // p = lane:  b = lane>>3, g = lane&7 ; p = lane+32: b = 4 + (lane>>3)
            int g  = lane & 7;
            int b0 = lane >> 3;
            int gl = gGroup * 8 + g;
            red[gl * 16 + (bGroup * 8 + b0)]     = keep0;
            red[gl * 16 + (bGroup * 8 + b0 + 4)] = keep1;
        }
        __syncthreads();
        if (kHalf == 0) {
            int g  = lane & 7;
            int b0 = lane >> 3;
            int gl = gGroup * 8 + g;
#pragma unroll
            for (int h = 0; h < 2; h++) {
                int bb = bGroup * 8 + b0 + h * 4;
                float v = (h ? keep1 : keep0) + red[gl * 16 + bb] + us[bb * 16 + gl];
                size_t o = ((size_t)(bb * T_ + t)) * H_ + gbase + gl;
                out[o] = v;
                if (t == T_ - 1)
                    out[(size_t)B_ * T_ * H_ + (size_t)bb * H_ + gbase + gl] = v;
            }
        }

        __threadfence();
        __syncthreads();
        if (tid == 0) atomicAdd((unsigned*)&g_arrive, 1u);
    }
}

extern "C" void kernel_launch(void* const* d_in, const int* in_sizes, int n_in,
                              void* d_out, int out_size)
{
    const float* x    = (const float*)d_in[0];   // [16, 512, 2048]
    const float* W    = (const float*)d_in[1];   // [2048, 4096]
    const float* bias = (const float*)d_in[2];   // [2048]
    float* out = (float*)d_out;                  // [16*512*2048 + 16*2048]

    float* U = nullptr;
    cudaGetSymbolAddress((void**)&U, g_u);

    cudaFuncSetAttribute(rnn_persistent_kernel,
                         cudaFuncAttributeMaxDynamicSharedMemorySize,
                         SMEM_FLOATS * sizeof(float));

    // reset grid-barrier counter (runs on every graph replay)
    init_kernel<<<1, 1>>>();

    // Phase 1: u = x @ Wx^T + b
    dim3 ggrid(H_ / TN, (B_ * T_) / TM);
    u_gemm_kernel<<<ggrid, 256>>>(x, W, bias, U);

    // Phase 2: persistent recurrence (writes all t and h_last)
    rnn_persistent_kernel<<<NCTA, NTHR, SMEM_FLOATS * sizeof(float)>>>(W, U, out);
}

// round 4
// speedup vs baseline: 1.6206x; 1.1278x over previous
#include <cuda_runtime.h>
#include <cuda_bf16.h>

// Problem constants
#define B_  16
#define T_  512
#define H_  2048
#define W_STRIDE 4096   // W is [H, 2H] row-major
#define NCTA 128
#define NTHR 256

// 64 MB scratch for u = x @ Wx^T + b   (B*T, H)
__device__ float g_u[B_ * T_ * H_];
// grid barrier counter (monotonic within one launch; reset per replay)
__device__ unsigned g_arrive;

__global__ void init_kernel() { g_arrive = 0u; }

// packed f32x2 FMA: d = a*b + c (elementwise on 2 packed floats)
__device__ __forceinline__ unsigned long long ffma2(
    unsigned long long a, unsigned long long b, unsigned long long c)
{
    unsigned long long d;
    asm("fma.rn.f32x2 %0, %1, %2, %3;" : "=l"(d) : "l"(a), "l"(b), "l"(c));
    return d;
}
// duplicate a float into both halves of an f32x2
__device__ __forceinline__ unsigned long long pack2(float x)
{
    unsigned long long r;
    asm("mov.b64 %0, {%1, %1};" : "=l"(r) : "f"(x));
    return r;
}
// grid-barrier primitives: no CCTL.IVALL (keep L1 resident!)
__device__ __forceinline__ void red_release_add(unsigned* p, unsigned v)
{
    asm volatile("red.release.gpu.global.add.u32 [%0], %1;" :: "l"(p), "r"(v) : "memory");
}
__device__ __forceinline__ unsigned ld_acquire(unsigned* p)
{
    unsigned v;
    asm volatile("ld.acquire.gpu.global.u32 %0, [%1];" : "=r"(v) : "l"(p) : "memory");
    return v;
}

// ---------------------------------------------------------------------------
// Phase 1: u[m, n] = sum_k X[m,k] * W[n, k] + bias[n]
// 128x128 tile, TK=8, 256 threads, 8x8 microtile, f32x2 packed FMA.
// ---------------------------------------------------------------------------
#define P1_TM 128
#define P1_TN 128
#define P1_TK 8

__global__ __launch_bounds__(256) void u_gemm_kernel(
    const float* __restrict__ X, const float* __restrict__ W,
    const float* __restrict__ bias, float* __restrict__ U)
{
    __shared__ __align__(16) float As[P1_TK][P1_TM + 4];
    __shared__ __align__(16) float Bs[P1_TK][P1_TN + 4];

    const int n0 = blockIdx.x * P1_TN;
    const int m0 = blockIdx.y * P1_TM;
    const int tid = threadIdx.x;
    const int tx = tid & 15;          // n microtile (8 cols)
    const int ty = tid >> 4;          // m microtile (8 rows)
    const int lrow = tid >> 1;        // load row (0..127)
    const int lk4  = (tid & 1) * 4;   // load k sub-block

    unsigned long long acc[8][4];     // [m][n-pair]
#pragma unroll
    for (int i = 0; i < 8; i++)
#pragma unroll
        for (int j = 0; j < 4; j++) acc[i][j] = 0ull;

    const float* xrow = X + (size_t)(m0 + lrow) * H_ + lk4;
    const float* wrow = W + (size_t)(n0 + lrow) * W_STRIDE + lk4;

    for (int k0 = 0; k0 < H_; k0 += P1_TK) {
        float4 xa = __ldg((const float4*)(xrow + k0));
        float4 wb = __ldg((const float4*)(wrow + k0));
        As[lk4 + 0][lrow] = xa.x; As[lk4 + 1][lrow] = xa.y;
        As[lk4 + 2][lrow] = xa.z; As[lk4 + 3][lrow] = xa.w;
        Bs[lk4 + 0][lrow] = wb.x; Bs[lk4 + 1][lrow] = wb.y;
        Bs[lk4 + 2][lrow] = wb.z; Bs[lk4 + 3][lrow] = wb.w;
        __syncthreads();

#pragma unroll
        for (int kk = 0; kk < P1_TK; kk++) {
            float4 a0 = *(const float4*)&As[kk][ty * 8];
            float4 a1 = *(const float4*)&As[kk][ty * 8 + 4];
            unsigned long long bp[4];
#pragma unroll
            for (int j = 0; j < 4; j++)
                bp[j] = *(const unsigned long long*)&Bs[kk][tx * 8 + j * 2];

            unsigned long long ap[8];
            ap[0] = pack2(a0.x); ap[1] = pack2(a0.y); ap[2] = pack2(a0.z); ap[3] = pack2(a0.w);
            ap[4] = pack2(a1.x); ap[5] = pack2(a1.y); ap[6] = pack2(a1.z); ap[7] = pack2(a1.w);
#pragma unroll
            for (int i = 0; i < 8; i++)
#pragma unroll
                for (int j = 0; j < 4; j++)
                    acc[i][j] = ffma2(ap[i], bp[j], acc[i][j]);
        }
        __syncthreads();
    }

#pragma unroll
    for (int i = 0; i < 8; i++) {
        size_t m = m0 + ty * 8 + i;
#pragma unroll
        for (int j = 0; j < 4; j++) {
            int n = n0 + tx * 8 + j * 2;
            float2 f = *(float2*)&acc[i][j];
            f.x += bias[n];
            f.y += bias[n + 1];
            *(float2*)&U[m * H_ + n] = f;
        }
    }
}

// ---------------------------------------------------------------------------
// Phase 2: persistent recurrence. 128 CTAs x 256 thr, 1 CTA/SM, spin barrier.
// CTA owns 16 g. Warp layout: gGroup(2 x 8g) x bGroup(2 x 8b) x kHalf(2 x 1024k).
// ---------------------------------------------------------------------------
#define SMEM_FLOATS (B_ * H_ + 256 + 256)

__global__ __launch_bounds__(NTHR, 1) void rnn_persistent_kernel(
    const float* __restrict__ W, const float* __restrict__ U,
    float* __restrict__ out)
{
    extern __shared__ __align__(16) float hs[];   // [16][2048]
    float* us  = hs + B_ * H_;                    // [16 b][16 gl]
    float* red = us + 256;                        // [16 gl][16 b]

    const int tid  = threadIdx.x;
    const int warp = tid >> 5;
    const int lane = tid & 31;
    const int gGroup = warp & 1;
    const int bGroup = (warp >> 1) & 1;
    const int kHalf  = warp >> 2;
    const int gbase = blockIdx.x * 16;

    const float* wb[8];
#pragma unroll
    for (int g = 0; g < 8; g++)
        wb[g] = W + (size_t)(gbase + gGroup * 8 + g) * W_STRIDE + H_ + kHalf * 1024;

    // ---- t = 0: out[:, 0, slice] = U[:, 0, slice] ----
    {
        int b = tid >> 4;
        int gl = tid & 15;
        int o = (b * T_) * H_ + gbase + gl;
        out[o] = __ldcg(&U[o]);
    }
    __syncthreads();
    if (tid == 0) red_release_add(&g_arrive, 1u);

    for (int t = 1; t < T_; t++) {
        // ---- grid barrier (acquire; no L1 flush) ----
        if (tid == 0) {
            unsigned target = (unsigned)(NCTA * t);
            while (ld_acquire(&g_arrive) < target) __nanosleep(32);
        }
        __syncthreads();

        // ---- stage h_{t-1} into smem via L2 (keep W hot in L1) ----
#pragma unroll 4
        for (int i = tid; i < (B_ * H_) / 4; i += NTHR) {
            int e = i * 4;
            int b = e >> 11;
            int k = e & (H_ - 1);
            float4 v = __ldcg((const float4*)&out[((size_t)(b * T_ + (t - 1))) * H_ + k]);
            *(float4*)&hs[b * H_ + k] = v;
        }
        {   // stage this step's U slice
            int b = tid >> 4;
            int gl = tid & 15;
            us[tid] = __ldcg(&U[((size_t)(b * T_ + t)) * H_ + gbase + gl]);
        }
        __syncthreads();

        // ---- compute: acc[b][g] as packed f32x2 ----
        unsigned long long acc[8][8];
#pragma unroll
        for (int b = 0; b < 8; b++)
#pragma unroll
            for (int g = 0; g < 8; g++) acc[b][g] = 0ull;

#pragma unroll
        for (int it = 0; it < 8; it++) {
            const int k0 = it * 128 + lane * 4;
            ulonglong2 wv[8];
#pragma unroll
            for (int g = 0; g < 8; g++)
                wv[g] = __ldg((const ulonglong2*)&wb[g][k0]);
#pragma unroll
            for (int b = 0; b < 8; b++) {
                ulonglong2 hv = *(const ulonglong2*)&hs[(bGroup * 8 + b) * H_ + kHalf * 1024 + k0];
#pragma unroll
                for (int g = 0; g < 8; g++) {
                    acc[b][g] = ffma2(hv.x, wv[g].x, acc[b][g]);
                    acc[b][g] = ffma2(hv.y, wv[g].y, acc[b][g]);
                }
            }
        }

        // ---- reduce across lanes; keep pair p at lane (p & 31) ----
        float keep0 = 0.f, keep1 = 0.f;
#pragma unroll
        for (int b = 0; b < 8; b++) {
#pragma unroll
            for (int g = 0; g < 8; g++) {
                float2 f2 = *(float2*)&acc[b][g];
                float p = f2.x + f2.y;
#pragma unroll
                for (int off = 16; off > 0; off >>= 1)
                    p += __shfl_xor_sync(0xffffffffu, p, off);
                int pidx = b * 8 + g;
                if (lane == (pidx & 31)) {
                    if (pidx < 32) keep0 = p; else keep1 = p;
                }
            }
        }

        // kHalf 1 publishes partials; kHalf 0 combines, adds U, stores.
        if (kHalf == 1) {
            int g  = lane & 7;
            int b0 = lane >> 3;
            int gl = gGroup * 8 + g;
            red[gl * 16 + (bGroup * 8 + b0)]     = keep0;
            red[gl * 16 + (bGroup * 8 + b0 + 4)] = keep1;
        }
        __syncthreads();
        if (kHalf == 0) {
            int g  = lane & 7;
            int b0 = lane >> 3;
            int gl = gGroup * 8 + g;
#pragma unroll
            for (int h = 0; h < 2; h++) {
                int bb = bGroup * 8 + b0 + h * 4;
                float v = (h ? keep1 : keep0) + red[gl * 16 + bb] + us[bb * 16 + gl];
                size_t o = ((size_t)(bb * T_ + t)) * H_ + gbase + gl;
                out[o] = v;
                if (t == T_ - 1)
                    out[(size_t)B_ * T_ * H_ + (size_t)bb * H_ + gbase + gl] = v;
            }
        }

        __syncthreads();
        if (tid == 0) red_release_add(&g_arrive, 1u);
    }
}

extern "C" void kernel_launch(void* const* d_in, const int* in_sizes, int n_in,
                              void* d_out, int out_size)
{
    const float* x    = (const float*)d_in[0];   // [16, 512, 2048]
    const float* W    = (const float*)d_in[1];   // [2048, 4096]
    const float* bias = (const float*)d_in[2];   // [2048]
    float* out = (float*)d_out;                  // [16*512*2048 + 16*2048]

    float* U = nullptr;
    cudaGetSymbolAddress((void**)&U, g_u);

    cudaFuncSetAttribute(rnn_persistent_kernel,
                         cudaFuncAttributeMaxDynamicSharedMemorySize,
                         SMEM_FLOATS * sizeof(float));

    // reset grid-barrier counter (runs on every graph replay)
    init_kernel<<<1, 1>>>();

    // Phase 1: u = x @ Wx^T + b
    dim3 ggrid(H_ / P1_TN, (B_ * T_) / P1_TM);
    u_gemm_kernel<<<ggrid, 256>>>(x, W, bias, U);

    // Phase 2: persistent recurrence (writes all t and h_last)
    rnn_persistent_kernel<<<NCTA, NTHR, SMEM_FLOATS * sizeof(float)>>>(W, U, out);
}